// round 1
// baseline (speedup 1.0000x reference)
#include <cuda_runtime.h>
#include <math.h>

#define Nn 50000
#define Ee 800000
#define HIDf 128
#define Gg 50
#define Lr 3

// ---------------- static device scratch (no runtime alloc allowed) ----------------
__device__ float g_qkvs[(size_t)Nn * 512];   // per layer: [q | k | v | x_r] each 128
__device__ float g_outb[(size_t)Nn * 128];   // attention output / gated output
__device__ float g_xcur[(size_t)Nn * 128];   // current node features (post layer)
__device__ float g_alpha[(size_t)Ee * 4];    // per-edge per-head logits -> exp weights
__device__ int   g_amax[(size_t)Nn * 4];     // ordered-int encoded segment max
__device__ float g_den[(size_t)Nn * 4];      // softmax denominators
__device__ float g_bnsum[128];
__device__ float g_bnsq[128];
__device__ float g_bnsc[128];
__device__ float g_bnsh[128];
__device__ int   g_esrc[Ee];
__device__ int   g_edst[Ee];
__device__ int   g_batch[Nn];
__device__ float g_gsum[Gg * 128];
__device__ float g_gcnt[Gg];
__device__ int   g_flags[2];

// ---------------- helpers ----------------
__device__ __forceinline__ int fenc(float f) {
    int i = __float_as_int(f);
    return i >= 0 ? i : i ^ 0x7fffffff;
}
__device__ __forceinline__ float fdec(int i) {
    return __int_as_float(i >= 0 ? i : i ^ 0x7fffffff);
}
#define ENC_NEG_INF 0x807fffff

// ---------------- dtype sniffing: int64 vs int32 index tensors ----------------
__global__ void k_detect(const void* ei, const void* ba) {
    if (threadIdx.x == 0 && blockIdx.x == 0) {
        // If underlying data is int64 (values < 2^31, non-negative), every odd
        // 32-bit word (high half, little-endian) is zero. Sample 64 positions
        // spread over the first half of the 32-bit view (safe for both dtypes).
        const unsigned int* p = (const unsigned int*)ei;
        unsigned int acc = 0;
        long long half_e = (long long)Ee - 1;  // i in [0, E): v=2i+1 < 2E
        for (int j = 0; j < 64; j++) {
            long long i = half_e * j / 63;
            acc |= p[2 * i + 1];
        }
        g_flags[0] = (acc == 0) ? 1 : 0;
        const unsigned int* q = (const unsigned int*)ba;
        unsigned int acc2 = 0;
        long long half_n = (long long)Nn / 2 - 1;
        for (int j = 0; j < 64; j++) {
            long long i = half_n * j / 63;
            acc2 |= q[2 * i + 1];
        }
        g_flags[1] = (acc2 == 0) ? 1 : 0;
    }
}

__global__ void k_convert(const void* ei, const void* ba) {
    int i = blockIdx.x * blockDim.x + threadIdx.x;
    int f0 = g_flags[0], f1 = g_flags[1];
    if (i < 2 * Ee) {
        int v = f0 ? (int)((const long long*)ei)[i] : ((const int*)ei)[i];
        if (i < Ee) g_esrc[i] = v;
        else        g_edst[i - Ee] = v;
    }
    if (i < Nn) {
        g_batch[i] = f1 ? (int)((const long long*)ba)[i] : ((const int*)ba)[i];
    }
}

// ---------------- per-layer init ----------------
__global__ void k_init() {
    int i = blockIdx.x * blockDim.x + threadIdx.x;
    if (i < Nn * 128) g_outb[i] = 0.0f;
    if (i < Nn * 4) { g_den[i] = 0.0f; g_amax[i] = ENC_NEG_INF; }
    if (i < 128) { g_bnsum[i] = 0.0f; g_bnsq[i] = 0.0f; }
}

// ---------------- fused q/k/v/skip GEMM: out[n, m*128+j] = x@W_m + b_m ----------------
// gridDim = (ceil(N/64), 4). 96KB dynamic smem: A tile 64x128, W 128x128.
__global__ void __launch_bounds__(256) k_gemm(
    const float* __restrict__ A,  // nullptr -> use g_xcur
    const float* __restrict__ W0, const float* __restrict__ W1,
    const float* __restrict__ W2, const float* __restrict__ W3,
    const float* __restrict__ b0, const float* __restrict__ b1,
    const float* __restrict__ b2, const float* __restrict__ b3)
{
    extern __shared__ float sm[];
    float (*As)[128] = (float (*)[128])sm;             // 64 rows
    float (*Bs)[128] = (float (*)[128])(sm + 64 * 128); // 128 rows

    const float* Ap = A ? A : g_xcur;
    int mat = blockIdx.y;
    const float* W = mat == 0 ? W0 : mat == 1 ? W1 : mat == 2 ? W2 : W3;
    const float* bias = mat == 0 ? b0 : mat == 1 ? b1 : mat == 2 ? b2 : b3;

    int tid = threadIdx.x;
    int row0 = blockIdx.x * 64;

    // load A tile: 64x128 floats = 2048 float4
    #pragma unroll
    for (int it = 0; it < 8; it++) {
        int idx = it * 256 + tid;
        int r = idx >> 5;
        int c4 = idx & 31;
        int gr = row0 + r;
        float4 v = (gr < Nn) ? ((const float4*)(Ap + (size_t)gr * 128))[c4]
                             : make_float4(0.f, 0.f, 0.f, 0.f);
        ((float4*)&As[r][0])[c4] = v;
    }
    // load W: 128x128 floats = 4096 float4
    #pragma unroll
    for (int it = 0; it < 16; it++) {
        int idx = it * 256 + tid;
        int r = idx >> 5;
        int c4 = idx & 31;
        ((float4*)&Bs[r][0])[c4] = ((const float4*)(W + r * 128))[c4];
    }
    __syncthreads();

    int tx = tid & 15, ty = tid >> 4;
    int mr = ty * 4, nc = tx * 8;
    float acc[4][8];
    #pragma unroll
    for (int r = 0; r < 4; r++)
        #pragma unroll
        for (int c = 0; c < 8; c++) acc[r][c] = 0.0f;

    #pragma unroll 8
    for (int k = 0; k < 128; k++) {
        float aa[4];
        aa[0] = As[mr + 0][k]; aa[1] = As[mr + 1][k];
        aa[2] = As[mr + 2][k]; aa[3] = As[mr + 3][k];
        float4 bv0 = *(const float4*)&Bs[k][nc];
        float4 bv1 = *(const float4*)&Bs[k][nc + 4];
        float bb[8] = {bv0.x, bv0.y, bv0.z, bv0.w, bv1.x, bv1.y, bv1.z, bv1.w};
        #pragma unroll
        for (int r = 0; r < 4; r++)
            #pragma unroll
            for (int c = 0; c < 8; c++)
                acc[r][c] = fmaf(aa[r], bb[c], acc[r][c]);
    }

    #pragma unroll
    for (int r = 0; r < 4; r++) {
        int gr = row0 + mr + r;
        if (gr < Nn) {
            float* o = g_qkvs + (size_t)gr * 512 + mat * 128 + nc;
            #pragma unroll
            for (int c = 0; c < 8; c++) o[c] = acc[r][c] + bias[nc + c];
        }
    }
}

// ---------------- attention logits + segment max (warp per edge) ----------------
__global__ void k_alpha(const float* __restrict__ edge_attr,
                        const float* __restrict__ We, const float* __restrict__ be)
{
    int wid = (blockIdx.x * blockDim.x + threadIdx.x) >> 5;
    int lane = threadIdx.x & 31;
    if (wid >= Ee) return;
    int src = g_esrc[wid], dst = g_edst[wid];
    float4 qv = ((const float4*)(g_qkvs + (size_t)dst * 512))[lane];
    float4 kv = ((const float4*)(g_qkvs + (size_t)src * 512 + 128))[lane];
    float a0 = edge_attr[wid * 2 + 0];
    float a1 = edge_attr[wid * 2 + 1];
    float4 w0 = ((const float4*)We)[lane];
    float4 w1 = ((const float4*)(We + 128))[lane];
    float4 bb = ((const float4*)be)[lane];
    float4 ee;
    ee.x = fmaf(a0, w0.x, fmaf(a1, w1.x, bb.x));
    ee.y = fmaf(a0, w0.y, fmaf(a1, w1.y, bb.y));
    ee.z = fmaf(a0, w0.z, fmaf(a1, w1.z, bb.z));
    ee.w = fmaf(a0, w0.w, fmaf(a1, w1.w, bb.w));
    float d = qv.x * (kv.x + ee.x) + qv.y * (kv.y + ee.y)
            + qv.z * (kv.z + ee.z) + qv.w * (kv.w + ee.w);
    d += __shfl_xor_sync(0xffffffffu, d, 4);
    d += __shfl_xor_sync(0xffffffffu, d, 2);
    d += __shfl_xor_sync(0xffffffffu, d, 1);
    if ((lane & 7) == 0) {
        int h = lane >> 3;
        float al = d * 0.17677669529663687f;  // 1/sqrt(32)
        g_alpha[(size_t)wid * 4 + h] = al;
        atomicMax(&g_amax[dst * 4 + h], fenc(al));
    }
}

// ---------------- exp + denominator (thread per edge-head) ----------------
__global__ void k_exp() {
    int i = blockIdx.x * blockDim.x + threadIdx.x;
    if (i >= Ee * 4) return;
    int e = i >> 2, h = i & 3;
    int dst = g_edst[e];
    float al = g_alpha[i];
    float m = fdec(g_amax[dst * 4 + h]);
    float ex = expf(al - m);
    g_alpha[i] = ex;
    atomicAdd(&g_den[dst * 4 + h], ex);
}

// ---------------- weighted message scatter (warp per edge) ----------------
__global__ void k_msg(const float* __restrict__ edge_attr,
                      const float* __restrict__ We, const float* __restrict__ be)
{
    int wid = (blockIdx.x * blockDim.x + threadIdx.x) >> 5;
    int lane = threadIdx.x & 31;
    if (wid >= Ee) return;
    int src = g_esrc[wid], dst = g_edst[wid];
    int h = lane >> 3;
    float ex = g_alpha[(size_t)wid * 4 + h];
    float den = g_den[dst * 4 + h];
    float w = ex / (den + 1e-16f);
    float4 vv = ((const float4*)(g_qkvs + (size_t)src * 512 + 256))[lane];
    float a0 = edge_attr[wid * 2 + 0];
    float a1 = edge_attr[wid * 2 + 1];
    float4 w0 = ((const float4*)We)[lane];
    float4 w1 = ((const float4*)(We + 128))[lane];
    float4 bb = ((const float4*)be)[lane];
    float mx = (vv.x + fmaf(a0, w0.x, fmaf(a1, w1.x, bb.x))) * w;
    float my = (vv.y + fmaf(a0, w0.y, fmaf(a1, w1.y, bb.y))) * w;
    float mz = (vv.z + fmaf(a0, w0.z, fmaf(a1, w1.z, bb.z))) * w;
    float mw = (vv.w + fmaf(a0, w0.w, fmaf(a1, w1.w, bb.w))) * w;
    float* o = g_outb + (size_t)dst * 128 + lane * 4;
    asm volatile("red.global.add.v4.f32 [%0], {%1,%2,%3,%4};"
                 :: "l"(o), "f"(mx), "f"(my), "f"(mz), "f"(mw) : "memory");
}

// ---------------- beta gate + BN partial stats (warp per node, 8 nodes/block) ----
__global__ void k_gate(const float* __restrict__ Wbeta) {
    __shared__ float ssum[128];
    __shared__ float ssq[128];
    int tid = threadIdx.x;
    if (tid < 128) { ssum[tid] = 0.0f; ssq[tid] = 0.0f; }
    __syncthreads();
    int lane = tid & 31;
    int n = blockIdx.x * 8 + (tid >> 5);
    if (n < Nn) {
        float4 o = ((const float4*)(g_outb + (size_t)n * 128))[lane];
        float4 xr = ((const float4*)(g_qkvs + (size_t)n * 512 + 384))[lane];
        float4 w1 = ((const float4*)Wbeta)[lane];
        float4 w2 = ((const float4*)(Wbeta + 128))[lane];
        float4 w3 = ((const float4*)(Wbeta + 256))[lane];
        float s = o.x * w1.x + o.y * w1.y + o.z * w1.z + o.w * w1.w
                + xr.x * w2.x + xr.y * w2.y + xr.z * w2.z + xr.w * w2.w
                + (o.x - xr.x) * w3.x + (o.y - xr.y) * w3.y
                + (o.z - xr.z) * w3.z + (o.w - xr.w) * w3.w;
        #pragma unroll
        for (int m = 16; m > 0; m >>= 1) s += __shfl_xor_sync(0xffffffffu, s, m);
        float g = 1.0f / (1.0f + expf(-s));
        float4 no;
        no.x = g * xr.x + (1.0f - g) * o.x;
        no.y = g * xr.y + (1.0f - g) * o.y;
        no.z = g * xr.z + (1.0f - g) * o.z;
        no.w = g * xr.w + (1.0f - g) * o.w;
        ((float4*)(g_outb + (size_t)n * 128))[lane] = no;
        int c = lane * 4;
        atomicAdd(&ssum[c + 0], no.x); atomicAdd(&ssq[c + 0], no.x * no.x);
        atomicAdd(&ssum[c + 1], no.y); atomicAdd(&ssq[c + 1], no.y * no.y);
        atomicAdd(&ssum[c + 2], no.z); atomicAdd(&ssq[c + 2], no.z * no.z);
        atomicAdd(&ssum[c + 3], no.w); atomicAdd(&ssq[c + 3], no.w * no.w);
    }
    __syncthreads();
    if (tid < 128) {
        atomicAdd(&g_bnsum[tid], ssum[tid]);
        atomicAdd(&g_bnsq[tid], ssq[tid]);
    }
}

// ---------------- BN finalize ----------------
__global__ void k_bnstats(const float* __restrict__ gamma, const float* __restrict__ beta) {
    int c = threadIdx.x;
    if (c < 128) {
        float mu = g_bnsum[c] / (float)Nn;
        float var = g_bnsq[c] / (float)Nn - mu * mu;
        float rs = rsqrtf(var + 1e-5f);
        float sc = gamma[c] * rs;
        g_bnsc[c] = sc;
        g_bnsh[c] = beta[c] - mu * sc;
    }
}

// ---------------- BN apply + ELU ----------------
__global__ void k_bnelu() {
    int i = blockIdx.x * blockDim.x + threadIdx.x;
    if (i >= Nn * 128) return;
    int c = i & 127;
    float y = g_outb[i] * g_bnsc[c] + g_bnsh[c];
    g_xcur[i] = y > 0.0f ? y : expm1f(y);
}

// ---------------- readout ----------------
__global__ void k_poolinit() {
    int i = blockIdx.x * blockDim.x + threadIdx.x;
    if (i < Gg * 128) g_gsum[i] = 0.0f;
    if (i < Gg) g_gcnt[i] = 0.0f;
}

__global__ void k_pool() {
    int wid = (blockIdx.x * blockDim.x + threadIdx.x) >> 5;
    int lane = threadIdx.x & 31;
    if (wid >= Nn) return;
    int b = g_batch[wid];
    float4 v = ((const float4*)(g_xcur + (size_t)wid * 128))[lane];
    float* o = g_gsum + b * 128 + lane * 4;
    atomicAdd(o + 0, v.x);
    atomicAdd(o + 1, v.y);
    atomicAdd(o + 2, v.z);
    atomicAdd(o + 3, v.w);
    if (lane == 0) atomicAdd(&g_gcnt[b], 1.0f);
}

__global__ void k_read(const float* __restrict__ Wout, const float* __restrict__ bout,
                       const float* __restrict__ obias, float* __restrict__ out) {
    __shared__ float red[128];
    int g = blockIdx.x;
    int c = threadIdx.x;
    float cnt = g_gcnt[g];
    float d = fmaxf(cnt, 1.0f);
    red[c] = g_gsum[g * 128 + c] / d * Wout[c];
    __syncthreads();
    for (int s = 64; s > 0; s >>= 1) {
        if (c < s) red[c] += red[c + s];
        __syncthreads();
    }
    if (c == 0) out[g] = red[0] + bout[0] + obias[0];
}

// ---------------- host ----------------
extern "C" void kernel_launch(void* const* d_in, const int* in_sizes, int n_in,
                              void* d_out, int out_size) {
    const float* x    = (const float*)d_in[0];
    const void*  ei   = d_in[1];
    const float* ea   = (const float*)d_in[2];
    const void*  ba   = d_in[3];
    const float* Wq   = (const float*)d_in[4];
    const float* bq   = (const float*)d_in[5];
    const float* Wk   = (const float*)d_in[6];
    const float* bk   = (const float*)d_in[7];
    const float* Wv   = (const float*)d_in[8];
    const float* bv   = (const float*)d_in[9];
    const float* We   = (const float*)d_in[10];
    const float* be   = (const float*)d_in[11];
    const float* Ws   = (const float*)d_in[12];
    const float* bs   = (const float*)d_in[13];
    const float* Wb   = (const float*)d_in[14];
    const float* gam  = (const float*)d_in[15];
    const float* bet  = (const float*)d_in[16];
    const float* Wout = (const float*)d_in[17];
    const float* bout = (const float*)d_in[18];
    const float* obia = (const float*)d_in[19];

    cudaFuncSetAttribute(k_gemm, cudaFuncAttributeMaxDynamicSharedMemorySize, 98304);

    k_detect<<<1, 32>>>(ei, ba);
    k_convert<<<(2 * Ee + 255) / 256, 256>>>(ei, ba);

    for (int l = 0; l < Lr; l++) {
        k_init<<<(Nn * 128 + 255) / 256, 256>>>();
        k_gemm<<<dim3((Nn + 63) / 64, 4), 256, 98304>>>(
            l == 0 ? x : nullptr,
            Wq + (size_t)l * 128 * 128, Wk + (size_t)l * 128 * 128,
            Wv + (size_t)l * 128 * 128, Ws + (size_t)l * 128 * 128,
            bq + l * 128, bk + l * 128, bv + l * 128, bs + l * 128);
        k_alpha<<<(Ee * 32) / 256, 256>>>(ea, We + l * 256, be + l * 128);
        k_exp<<<(Ee * 4 + 255) / 256, 256>>>();
        k_msg<<<(Ee * 32) / 256, 256>>>(ea, We + l * 256, be + l * 128);
        k_gate<<<(Nn + 7) / 8, 256>>>(Wb + l * 384);
        k_bnstats<<<1, 128>>>(gam + l * 128, bet + l * 128);
        k_bnelu<<<(Nn * 128 + 255) / 256, 256>>>();
    }

    k_poolinit<<<(Gg * 128 + 255) / 256, 256>>>();
    k_pool<<<(Nn * 32 + 255) / 256, 256>>>();
    k_read<<<Gg, 128>>>(Wout, bout, obia, (float*)d_out);
}